// round 4
// baseline (speedup 1.0000x reference)
#include <cuda_runtime.h>
#include <math.h>

#define D        64
#define MQ       32
#define TK       64
#define TOPK     32
#define THREADS  256
#define NSPLIT   4
#define MAXROWS  4096
#define NEG_INF  (-3.402823466e38f)

typedef unsigned long long u64;

// partial-result scratch (static device memory; no allocation)
__device__ float g_ptsc [NSPLIT * MAXROWS * TOPK];
__device__ int   g_ptix [NSPLIT * MAXROWS * TOPK];
__device__ float g_psumv[NSPLIT * MAXROWS * D];
__device__ float g_pcnt [NSPLIT * MAXROWS];

struct __align__(16) Smem {
    float Qs[MQ * D];          // chunk-swizzled by (row>>1)
    float Ks[TK * D];          // chunk-swizzled by (row>>2)
    float Vs[TK][D];           // plain [l][d]
    float Ss[MQ][D + 4];       // scores [q][k]
    u64   Msd[TK][MQ];         // duplicated mask pair (m,m) per (l,q)
    float tsc[MQ][TOPK];
    int   tix[MQ][TOPK];
    u64   Mbits[MQ];
    u64   cand[MQ];
    float thr[MQ];
};

__device__ __forceinline__ void fma2(u64& d, u64 a, u64 b) {
    asm("fma.rn.f32x2 %0, %1, %2, %0;" : "+l"(d) : "l"(a), "l"(b));
}
__device__ __forceinline__ float2 up2(u64 a) {
    float2 r;
    asm("mov.b64 {%0,%1}, %2;" : "=f"(r.x), "=f"(r.y) : "l"(a));
    return r;
}
__device__ __forceinline__ int qswz(int r, int d) {   // Q smem index
    return r * D + ((((d >> 2) + (r >> 1)) & 15) << 2) + (d & 3);
}
__device__ __forceinline__ int kswz(int r, int d) {   // K smem index
    return r * D + ((((d >> 2) + (r >> 2)) & 15) << 2) + (d & 3);
}

__global__ __launch_bounds__(THREADS, 3)
void ga_part(const float* __restrict__ q, const float* __restrict__ k,
             const float* __restrict__ v, const int* __restrict__ mask,
             int B, int Lq, int L, int N)
{
    extern __shared__ unsigned char smem_raw[];
    Smem* S = reinterpret_cast<Smem*>(smem_raw);

    const int tid   = threadIdx.x;
    const int b     = blockIdx.y;
    const int q0g   = blockIdx.x * MQ;
    const int split = blockIdx.z;
    const int LC    = L / NSPLIT;
    const int lbeg  = split * LC;
    const int row0  = b * Lq + q0g;
    const int vrow0 = b * L;

    // ---- init ----
    for (int j = tid; j < MQ * D; j += THREADS) {
        int qi = j >> 6, d = j & 63;
        S->Qs[qswz(qi, d)] = q[((size_t)row0 + qi) * D + d] * 0.125f;  // 1/sqrt(64)
    }
    for (int j = tid; j < MQ * TOPK; j += THREADS) {
        S->tsc[j >> 5][j & 31] = NEG_INF;
        S->tix[j >> 5][j & 31] = -1;
    }
    if (tid < MQ) {
        S->thr[tid]   = NEG_INF;
        S->Mbits[tid] = 0ull;
        S->cand[tid]  = 0ull;
    }
    __syncthreads();

    const int wid  = tid >> 5;
    const int lane = tid & 31;
    // score mapping (warps 0-3): thread tile 2q x 8k
    const int kc = 8 * (lane & 3) + 32 * (wid & 1);
    const int qa = 2 * (lane >> 2) + 16 * (wid >> 1);
    // mask*V mapping (warps 4-7): thread tile 4q x 4d
    const int wm = wid - 4;
    const int dc = 4 * (lane & 7) + 32 * (wm & 1);
    const int qb = 4 * (lane >> 3) + 16 * (wm >> 1);

    u64 mv[8];
    #pragma unroll
    for (int i = 0; i < 8; i++) mv[i] = 0ull;

    float thrL = NEG_INF;   // merge state (tid < MQ)
    int   minpos = 0;
    float cntL = 0.0f;

    const size_t kb = (size_t)b * L * D;

    for (int lt = 0; lt < LC; lt += TK) {
        const int l0 = lbeg + lt;

        // ===== load tile =====
        #pragma unroll
        for (int r = 0; r < 4; r++) {
            int idx4 = tid + THREADS * r;
            int i  = idx4 >> 4;
            int c4 = (idx4 & 15) << 2;
            const float4 tk = *(const float4*)(k + kb + (size_t)(l0 + i) * D + c4);
            *(float4*)&S->Ks[i * D + ((((c4 >> 2) + (i >> 2)) & 15) << 2)] = tk;
            const float4 tv = *(const float4*)(v + kb + (size_t)(l0 + i) * D + c4);
            *(float4*)&S->Vs[i][c4] = tv;
        }
        {
            int qi = tid >> 3, c8 = (tid & 7) << 3;
            const int4* mp = (const int4*)(mask + (size_t)(row0 + qi) * L + l0 + c8);
            int4 m0 = mp[0];
            int4 m1 = mp[1];
            int mm[8] = { m0.x, m0.y, m0.z, m0.w, m1.x, m1.y, m1.z, m1.w };
            u64 bits = 0ull;
            #pragma unroll
            for (int jj = 0; jj < 8; jj++) {
                int on = (mm[jj] != 0);
                bits |= (u64)on << (c8 + jj);
                unsigned int fb = __float_as_uint((float)on);
                S->Msd[c8 + jj][qi] = (u64)fb | ((u64)fb << 32);
            }
            if (bits) atomicOr(&S->Mbits[qi], bits);
        }
        __syncthreads();

        // ===== compute (specialized) =====
        if (wid < 4) {
            const float thr0 = S->thr[qa];
            const float thr1 = S->thr[qa + 1];
            const u64   Mb0  = S->Mbits[qa];
            const u64   Mb1  = S->Mbits[qa + 1];
            u64 sp0[8], sp1[8];
            #pragma unroll
            for (int j = 0; j < 8; j++) { sp0[j] = 0ull; sp1[j] = 0ull; }

            #pragma unroll 4
            for (int d = 0; d < D; d += 2) {
                u64 Q0 = *(const u64*)&S->Qs[qswz(qa,     d)];
                u64 Q1 = *(const u64*)&S->Qs[qswz(qa + 1, d)];
                #pragma unroll
                for (int j = 0; j < 8; j++) {
                    u64 Kj = *(const u64*)&S->Ks[kswz(kc + j, d)];
                    fma2(sp0[j], Q0, Kj);
                    fma2(sp1[j], Q1, Kj);
                }
            }
            u64 w0 = 0ull, w1 = 0ull;
            #pragma unroll
            for (int j = 0; j < 8; j++) {
                int kp = kc + j;
                float2 p0 = up2(sp0[j]);
                float  s0 = p0.x + p0.y;
                S->Ss[qa][kp] = s0;
                if (s0 > thr0 && ((Mb0 >> kp) & 1ull)) w0 |= 1ull << kp;
                float2 p1 = up2(sp1[j]);
                float  s1 = p1.x + p1.y;
                S->Ss[qa + 1][kp] = s1;
                if (s1 > thr1 && ((Mb1 >> kp) & 1ull)) w1 |= 1ull << kp;
            }
            if (w0) atomicOr(&S->cand[qa],     w0);
            if (w1) atomicOr(&S->cand[qa + 1], w1);
        } else {
            #pragma unroll 4
            for (int l = 0; l < TK; l++) {
                ulonglong2 v2 = *(const ulonglong2*)&S->Vs[l][dc];
                ulonglong2 ma = *(const ulonglong2*)&S->Msd[l][qb];
                ulonglong2 mb = *(const ulonglong2*)&S->Msd[l][qb + 2];
                fma2(mv[0], ma.x, v2.x); fma2(mv[1], ma.x, v2.y);
                fma2(mv[2], ma.y, v2.x); fma2(mv[3], ma.y, v2.y);
                fma2(mv[4], mb.x, v2.x); fma2(mv[5], mb.x, v2.y);
                fma2(mv[6], mb.y, v2.x); fma2(mv[7], mb.y, v2.y);
            }
        }
        __syncthreads();

        // ===== merge candidates =====
        if (tid < MQ) {
            const int qq = tid;
            u64 w = S->cand[qq];
            cntL += (float)__popcll(S->Mbits[qq]);
            while (w) {
                int kk = __ffsll((long long)w) - 1;
                w &= w - 1ull;
                float s = S->Ss[qq][kk];
                if (s > thrL) {
                    S->tsc[qq][minpos] = s;
                    S->tix[qq][minpos] = vrow0 + l0 + kk;   // global v-row
                    float nm = S->tsc[qq][0]; int np = 0;
                    #pragma unroll
                    for (int i = 1; i < TOPK; i++) {
                        float ti = S->tsc[qq][i];
                        if (ti < nm) { nm = ti; np = i; }
                    }
                    thrL = nm; minpos = np;
                }
            }
            S->thr[qq]   = thrL;
            S->Mbits[qq] = 0ull;
            S->cand[qq]  = 0ull;
        }
        __syncthreads();
    }

    // ===== write partials =====
    if (wid >= 4) {
        #pragma unroll
        for (int qi = 0; qi < 4; qi++) {
            float2 a = up2(mv[qi * 2]);
            float2 c = up2(mv[qi * 2 + 1]);
            size_t off = ((size_t)split * N + row0 + qb + qi) * D + dc;
            *(float4*)&g_psumv[off] = make_float4(a.x, a.y, c.x, c.y);
        }
    }
    if (tid < MQ) g_pcnt[(size_t)split * N + row0 + tid] = cntL;
    for (int j = tid; j < MQ * TOPK; j += THREADS) {
        int qq = j >> 5, i = j & 31;
        size_t off = ((size_t)split * N + row0 + qq) * TOPK + i;
        g_ptsc[off] = S->tsc[qq][i];
        g_ptix[off] = S->tix[qq][i];
    }
}

__global__ __launch_bounds__(256)
void ga_merge(const float* __restrict__ v, float* __restrict__ out, int N)
{
    const int wid  = threadIdx.x >> 5;
    const int lane = threadIdx.x & 31;
    const int n    = blockIdx.x * 8 + wid;
    if (n >= N) return;

    float cs[NSPLIT];
    int   ci[NSPLIT];
    #pragma unroll
    for (int s = 0; s < NSPLIT; s++) {
        size_t off = ((size_t)s * N + n) * TOPK + lane;
        cs[s] = g_ptsc[off];
        ci[s] = g_ptix[off];
    }

    // exact top-32 of 128 candidates: iterated warp argmax (ties -> lower idx)
    float selS = NEG_INF;
    int   selI = -1;
    for (int it = 0; it < TOPK; it++) {
        float bs = cs[0]; int bi = ci[0]; int slot = 0;
        #pragma unroll
        for (int s = 1; s < NSPLIT; s++) {
            if (cs[s] > bs || (cs[s] == bs && (unsigned)ci[s] < (unsigned)bi)) {
                bs = cs[s]; bi = ci[s]; slot = s;
            }
        }
        int meta = (lane << 2) | slot;
        #pragma unroll
        for (int off = 16; off > 0; off >>= 1) {
            float os = __shfl_xor_sync(0xFFFFFFFFu, bs, off);
            int   oi = __shfl_xor_sync(0xFFFFFFFFu, bi, off);
            int   om = __shfl_xor_sync(0xFFFFFFFFu, meta, off);
            if (os > bs || (os == bs && (unsigned)oi < (unsigned)bi)) {
                bs = os; bi = oi; meta = om;
            }
        }
        if ((meta >> 2) == lane) { cs[meta & 3] = NEG_INF; ci[meta & 3] = -1; }
        if (lane == it) { selS = bs; selI = bi; }
    }

    // softmax over selected
    bool  valid = (selI >= 0);
    float sv = valid ? selS : NEG_INF;
    float m = sv;
    #pragma unroll
    for (int off = 16; off > 0; off >>= 1)
        m = fmaxf(m, __shfl_xor_sync(0xFFFFFFFFu, m, off));
    float e = valid ? expf(selS - m) : 0.0f;
    float den = e;
    #pragma unroll
    for (int off = 16; off > 0; off >>= 1)
        den += __shfl_xor_sync(0xFFFFFFFFu, den, off);
    float wgt = (den > 0.0f) ? (e / den) : 0.0f;

    // gather V
    float a0 = 0.0f, a1 = 0.0f;
    #pragma unroll 1
    for (int i = 0; i < TOPK; i++) {
        float wi = __shfl_sync(0xFFFFFFFFu, wgt, i);
        int   ii = __shfl_sync(0xFFFFFFFFu, selI, i);
        if (ii >= 0) {
            const float* vr = v + (size_t)ii * D;
            a0 = fmaf(wi, vr[lane],      a0);
            a1 = fmaf(wi, vr[lane + 32], a1);
        }
    }

    // mean pool + combine
    float sv0 = 0.0f, sv1 = 0.0f, c = 0.0f;
    #pragma unroll
    for (int s = 0; s < NSPLIT; s++) {
        size_t off = ((size_t)s * N + n) * D;
        sv0 += g_psumv[off + lane];
        sv1 += g_psumv[off + lane + 32];
        c   += g_pcnt[(size_t)s * N + n];
    }
    c = fmaxf(c, 1.0f);
    out[(size_t)n * D + lane]      = sv0 / c + a0;
    out[(size_t)n * D + lane + 32] = sv1 / c + a1;
}

extern "C" void kernel_launch(void* const* d_in, const int* in_sizes, int n_in,
                              void* d_out, int out_size)
{
    const float* q = (const float*)d_in[0];
    const float* k = (const float*)d_in[1];
    const float* v = (const float*)d_in[2];
    const int*   mask = (const int*)d_in[3];
    float* out = (float*)d_out;

    int N    = in_sizes[0] / D;    // B * Lq
    int Ktot = in_sizes[1] / D;    // B * L
    int L    = in_sizes[3] / N;
    int B    = Ktot / L;
    int Lq   = N / B;

    int smem = (int)sizeof(Smem);
    cudaFuncSetAttribute(ga_part, cudaFuncAttributeMaxDynamicSharedMemorySize, smem);

    dim3 grid(Lq / MQ, B, NSPLIT);
    ga_part<<<grid, THREADS, smem>>>(q, k, v, mask, B, Lq, L, N);
    ga_merge<<<(N + 7) / 8, 256>>>(v, out, N);
}

// round 5
// speedup vs baseline: 1.0361x; 1.0361x over previous
#include <cuda_runtime.h>
#include <math.h>

#define D        64
#define MQ       32
#define TK       64
#define TOPK     32
#define THREADS  512
#define NEG_INF  (-3.402823466e38f)

typedef unsigned long long u64;

struct __align__(16) Smem {
    float Qs[MQ][D + 4];       // pre-scaled q [q][d], stride 68
    float Ks[TK][D + 4];       // k tile [l][d], stride 68
    float Vs[TK][D];           // v tile [l][d]
    float Ss[MQ][D + 4];       // scores [q][k] / final mask*V sums [q][d]
    float tsc[MQ][TOPK];       // top-k scores
    int   tix[MQ][TOPK];       // top-k indices
    u64   Mbits[MQ];           // mask bits of current tile
    u64   cand[MQ];            // candidate bits of current tile
    float thr[MQ];             // current heap-min per query
    float cnt[MQ];
};

__device__ __forceinline__ void fma2(u64& d, u64 a, u64 b) {
    asm("fma.rn.f32x2 %0, %1, %2, %0;" : "+l"(d) : "l"(a), "l"(b));
}
__device__ __forceinline__ float2 up2(u64 a) {
    float2 r;
    asm("mov.b64 {%0,%1}, %2;" : "=f"(r.x), "=f"(r.y) : "l"(a));
    return r;
}
// predicated: if (t != 0) { a0 += vx; a1 += vy; }  (packed f32x2 adds)
__device__ __forceinline__ void madd2(u64& a0, u64& a1, unsigned t, u64 vx, u64 vy) {
    asm volatile("{\n\t.reg .pred p;\n\tsetp.ne.u32 p, %2, 0;\n\t"
                 "@p add.rn.f32x2 %0, %0, %3;\n\t"
                 "@p add.rn.f32x2 %1, %1, %4;\n\t}"
                 : "+l"(a0), "+l"(a1) : "r"(t), "l"(vx), "l"(vy));
}

__global__ __launch_bounds__(THREADS)
void ga_kernel(const float* __restrict__ q, const float* __restrict__ k,
               const float* __restrict__ v, const int* __restrict__ mask,
               float* __restrict__ out, int B, int Lq, int L)
{
    extern __shared__ unsigned char smem_raw[];
    Smem* S = reinterpret_cast<Smem*>(smem_raw);

    const int tid  = threadIdx.x;
    const int b    = blockIdx.y;
    const int q0g  = blockIdx.x * MQ;
    const int row0 = b * Lq + q0g;

    // score warps (0-7): thread tile 2q x 4k  (tid 0..255)
    const int qa = 2 * ((tid & 255) >> 4);
    const int kc = 4 * (tid & 15);
    // mask*V warps (8-15): thread tile 2q x 4d (same index math on tid-256)
    const int dc = kc;

    // ---- init ----
    for (int j = tid; j < MQ * D; j += THREADS) {
        int qi = j >> 6, d = j & 63;
        S->Qs[qi][d] = q[((size_t)row0 + qi) * D + d] * 0.125f;   // 1/sqrt(64)
    }
    for (int j = tid; j < MQ * TOPK; j += THREADS) {
        S->tsc[j >> 5][j & 31] = NEG_INF;
        S->tix[j >> 5][j & 31] = -1;
    }
    if (tid < MQ) {
        S->thr[tid]  = NEG_INF;
        S->cand[tid] = 0ull;
    }

    u64 mv[4];                               // persistent mask*V accum (warps 8-15)
    #pragma unroll
    for (int i = 0; i < 4; i++) mv[i] = 0ull;

    float thrL = NEG_INF;                    // merge state (tid < MQ)
    int   minpos = 0;
    float cntL = 0.0f;

    const size_t kb = (size_t)b * L * D;

    for (int l0 = 0; l0 < L; l0 += TK) {
        // ================= load tile =================
        #pragma unroll
        for (int r = 0; r < 2; r++) {
            int idx4 = tid + THREADS * r;
            int i  = idx4 >> 4;
            int c4 = (idx4 & 15) << 2;
            *(float4*)&S->Ks[i][c4] = *(const float4*)(k + kb + (size_t)(l0 + i) * D + c4);
            *(float4*)&S->Vs[i][c4] = *(const float4*)(v + kb + (size_t)(l0 + i) * D + c4);
        }
        {   // mask: 1 int4 per thread -> 4 bits; OR-reduce over 16 lanes; 1 STS
            int qi = tid >> 4, c4 = (tid & 15) << 2;
            int4 mm = *(const int4*)(mask + (size_t)(row0 + qi) * L + l0 + c4);
            u64 bits = ((u64)(mm.x != 0) << c4)       | ((u64)(mm.y != 0) << (c4 + 1))
                     | ((u64)(mm.z != 0) << (c4 + 2)) | ((u64)(mm.w != 0) << (c4 + 3));
            #pragma unroll
            for (int off = 1; off < 16; off <<= 1)
                bits |= __shfl_xor_sync(0xFFFFFFFFu, bits, off);
            if ((tid & 15) == 0) S->Mbits[qi] = bits;
        }
        __syncthreads();

        // ================= compute (two warp groups) =================
        if (tid < 256) {
            // ---- scores: 2q x 4k, f32x2 pairwise over d ----
            const float thr0 = S->thr[qa];
            const float thr1 = S->thr[qa + 1];
            const u64   Mb0  = S->Mbits[qa];
            const u64   Mb1  = S->Mbits[qa + 1];
            u64 sp0[4], sp1[4];
            #pragma unroll
            for (int j = 0; j < 4; j++) { sp0[j] = 0ull; sp1[j] = 0ull; }

            #pragma unroll 4
            for (int d = 0; d < D; d += 4) {
                ulonglong2 Q0 = *(const ulonglong2*)&S->Qs[qa][d];
                ulonglong2 Q1 = *(const ulonglong2*)&S->Qs[qa + 1][d];
                #pragma unroll
                for (int j = 0; j < 4; j++) {
                    ulonglong2 Kj = *(const ulonglong2*)&S->Ks[kc + j][d];
                    fma2(sp0[j], Q0.x, Kj.x);
                    fma2(sp0[j], Q0.y, Kj.y);
                    fma2(sp1[j], Q1.x, Kj.x);
                    fma2(sp1[j], Q1.y, Kj.y);
                }
            }
            float s0v[4], s1v[4];
            u64 w0 = 0ull, w1 = 0ull;
            #pragma unroll
            for (int j = 0; j < 4; j++) {
                int kp = kc + j;
                float2 p0 = up2(sp0[j]);
                s0v[j] = p0.x + p0.y;
                if (s0v[j] > thr0 && ((Mb0 >> kp) & 1ull)) w0 |= 1ull << kp;
                float2 p1 = up2(sp1[j]);
                s1v[j] = p1.x + p1.y;
                if (s1v[j] > thr1 && ((Mb1 >> kp) & 1ull)) w1 |= 1ull << kp;
            }
            *(float4*)&S->Ss[qa][kc]     = make_float4(s0v[0], s0v[1], s0v[2], s0v[3]);
            *(float4*)&S->Ss[qa + 1][kc] = make_float4(s1v[0], s1v[1], s1v[2], s1v[3]);
            if (w0) atomicOr(&S->cand[qa],     w0);
            if (w1) atomicOr(&S->cand[qa + 1], w1);
        } else {
            // ---- mask*V: 2q x 4d, predicated packed adds ----
            const u64 Mb0 = S->Mbits[qa];
            const u64 Mb1 = S->Mbits[qa + 1];
            const unsigned m0l = (unsigned)Mb0, m0h = (unsigned)(Mb0 >> 32);
            const unsigned m1l = (unsigned)Mb1, m1h = (unsigned)(Mb1 >> 32);
            #pragma unroll
            for (int l = 0; l < TK; l++) {
                ulonglong2 v2 = *(const ulonglong2*)&S->Vs[l][dc];
                unsigned t0 = ((l < 32) ? m0l : m0h) & (1u << (l & 31));
                unsigned t1 = ((l < 32) ? m1l : m1h) & (1u << (l & 31));
                madd2(mv[0], mv[1], t0, v2.x, v2.y);
                madd2(mv[2], mv[3], t1, v2.x, v2.y);
            }
        }
        __syncthreads();

        // ================= merge candidates =================
        if (tid < MQ) {
            const int qq = tid;
            u64 w = S->cand[qq];
            cntL += (float)__popcll(S->Mbits[qq]);
            while (w) {
                int kk = __ffsll((long long)w) - 1;
                w &= w - 1ull;
                float s = S->Ss[qq][kk];
                if (s > thrL) {
                    S->tsc[qq][minpos] = s;
                    S->tix[qq][minpos] = l0 + kk;
                    float nm = S->tsc[qq][0]; int np = 0;
                    #pragma unroll
                    for (int i = 1; i < TOPK; i++) {
                        float ti = S->tsc[qq][i];
                        if (ti < nm) { nm = ti; np = i; }
                    }
                    thrL = nm; minpos = np;
                }
            }
            S->thr[qq]  = thrL;
            S->cand[qq] = 0ull;
        }
        __syncthreads();
    }

    // ---- dump mask*V sums into Ss [q][d] ----
    if (tid >= 256) {
        float2 a = up2(mv[0]), bq = up2(mv[1]);
        *(float4*)&S->Ss[qa][dc] = make_float4(a.x, a.y, bq.x, bq.y);
        float2 c = up2(mv[2]), dq = up2(mv[3]);
        *(float4*)&S->Ss[qa + 1][dc] = make_float4(c.x, c.y, dq.x, dq.y);
    }
    if (tid < MQ) S->cnt[tid] = cntL;
    __syncthreads();

    // ---- epilogue: softmax over top-32, gather V, add mean ----
    const int wid  = tid >> 5;
    const int lane = tid & 31;
    const float* vb = v + kb;
    for (int qq = wid; qq < MQ; qq += (THREADS / 32)) {
        float s  = S->tsc[qq][lane];
        int   ix = S->tix[qq][lane];
        bool valid = (ix >= 0);
        float sv = valid ? s : NEG_INF;
        float m = sv;
        #pragma unroll
        for (int off = 16; off > 0; off >>= 1)
            m = fmaxf(m, __shfl_xor_sync(0xFFFFFFFFu, m, off));
        float e = valid ? expf(s - m) : 0.0f;
        float den = e;
        #pragma unroll
        for (int off = 16; off > 0; off >>= 1)
            den += __shfl_xor_sync(0xFFFFFFFFu, den, off);
        float w = (den > 0.0f) ? (e / den) : 0.0f;

        float a0 = 0.0f, a1 = 0.0f;
        #pragma unroll 1
        for (int i = 0; i < TOPK; i++) {
            float wi = __shfl_sync(0xFFFFFFFFu, w, i);
            int   ii = __shfl_sync(0xFFFFFFFFu, ix, i);
            if (ii >= 0) {
                const float* vr = vb + (size_t)ii * D;
                a0 = fmaf(wi, vr[lane],      a0);
                a1 = fmaf(wi, vr[lane + 32], a1);
            }
        }
        float c = fmaxf(S->cnt[qq], 1.0f);
        size_t obase = ((size_t)(row0 + qq)) * D;
        out[obase + lane]      = S->Ss[qq][lane]      / c + a0;
        out[obase + lane + 32] = S->Ss[qq][lane + 32] / c + a1;
    }
}

extern "C" void kernel_launch(void* const* d_in, const int* in_sizes, int n_in,
                              void* d_out, int out_size)
{
    const float* q = (const float*)d_in[0];
    const float* k = (const float*)d_in[1];
    const float* v = (const float*)d_in[2];
    const int*   mask = (const int*)d_in[3];
    float* out = (float*)d_out;

    int N    = in_sizes[0] / D;    // B * Lq
    int Ktot = in_sizes[1] / D;    // B * L
    int L    = in_sizes[3] / N;
    int B    = Ktot / L;
    int Lq   = N / B;

    int smem = (int)sizeof(Smem);
    cudaFuncSetAttribute(ga_kernel, cudaFuncAttributeMaxDynamicSharedMemorySize, smem);

    dim3 grid(Lq / MQ, B);
    ga_kernel<<<grid, THREADS, smem>>>(q, k, v, mask, out, B, Lq, L);
}

// round 6
// speedup vs baseline: 1.5050x; 1.4526x over previous
#include <cuda_runtime.h>
#include <math.h>

#define D        64
#define MQ       32
#define TK       64
#define TOPK     32
#define THREADS  512
#define NEG_INF  (-3.402823466e38f)

typedef unsigned long long u64;

struct __align__(16) Smem {
    float Qs[MQ][D + 4];       // pre-scaled q [q][d], stride 68
    float Ks[TK][D + 4];       // k tile [l][d], stride 68
    float Vs[TK][D];           // v tile [l][d]
    float Ss[MQ][D + 4];       // scores [q][k] / final mask*V sums [q][d]
    float tsc[MQ][TOPK];       // top-k scores
    int   tix[MQ][TOPK];       // top-k indices
    u64   Mbits[MQ];           // mask bits of current tile
    u64   cand[MQ];            // candidate bits of current tile
    float thr[MQ];             // current heap-min per query
    float cnt[MQ];
};

__device__ __forceinline__ void fma2(u64& d, u64 a, u64 b) {
    asm("fma.rn.f32x2 %0, %1, %2, %0;" : "+l"(d) : "l"(a), "l"(b));
}
__device__ __forceinline__ float2 up2(u64 a) {
    float2 r;
    asm("mov.b64 {%0,%1}, %2;" : "=f"(r.x), "=f"(r.y) : "l"(a));
    return r;
}
// predicated: if (t != 0) { a0 += vx; a1 += vy; }  (packed f32x2 adds)
__device__ __forceinline__ void madd2(u64& a0, u64& a1, unsigned t, u64 vx, u64 vy) {
    asm volatile("{\n\t.reg .pred p;\n\tsetp.ne.u32 p, %2, 0;\n\t"
                 "@p add.rn.f32x2 %0, %0, %3;\n\t"
                 "@p add.rn.f32x2 %1, %1, %4;\n\t}"
                 : "+l"(a0), "+l"(a1) : "r"(t), "l"(vx), "l"(vy));
}

__global__ __launch_bounds__(THREADS)
void ga_kernel(const float* __restrict__ q, const float* __restrict__ k,
               const float* __restrict__ v, const int* __restrict__ mask,
               float* __restrict__ out, int B, int Lq, int L)
{
    extern __shared__ unsigned char smem_raw[];
    Smem* S = reinterpret_cast<Smem*>(smem_raw);

    const int tid  = threadIdx.x;
    const int b    = blockIdx.y;
    const int q0g  = blockIdx.x * MQ;
    const int row0 = b * Lq + q0g;

    const int t15 = tid & 15;
    // score warps (0-7): thread tile 2q x 4k, k rows STRIDED {t15+16j} (bank-conflict-free)
    const int qa = 2 * ((tid & 255) >> 4);
    // mask*V warps (8-15): thread tile 2q x 4d
    const int dc = 4 * t15;

    // ---- init ----
    for (int j = tid; j < MQ * D; j += THREADS) {
        int qi = j >> 6, d = j & 63;
        S->Qs[qi][d] = q[((size_t)row0 + qi) * D + d] * 0.125f;   // 1/sqrt(64)
    }
    for (int j = tid; j < MQ * TOPK; j += THREADS) {
        S->tsc[j >> 5][j & 31] = NEG_INF;
        S->tix[j >> 5][j & 31] = -1;
    }
    if (tid < MQ) {
        S->thr[tid]  = NEG_INF;
        S->cand[tid] = 0ull;
    }

    u64 mv[4];                               // persistent mask*V accum (warps 8-15)
    #pragma unroll
    for (int i = 0; i < 4; i++) mv[i] = 0ull;

    float thrL = NEG_INF;                    // merge state (tid < MQ)
    int   minpos = 0;
    float cntL = 0.0f;

    const size_t kb = (size_t)b * L * D;

    for (int l0 = 0; l0 < L; l0 += TK) {
        // ================= load tile =================
        #pragma unroll
        for (int r = 0; r < 2; r++) {
            int idx4 = tid + THREADS * r;
            int i  = idx4 >> 4;
            int c4 = (idx4 & 15) << 2;
            *(float4*)&S->Ks[i][c4] = *(const float4*)(k + kb + (size_t)(l0 + i) * D + c4);
            *(float4*)&S->Vs[i][c4] = *(const float4*)(v + kb + (size_t)(l0 + i) * D + c4);
        }
        {   // mask: 1 int4 per thread -> 4 bits; OR-reduce over 16 lanes; 1 STS
            int qi = tid >> 4, c4 = (tid & 15) << 2;
            int4 mm = *(const int4*)(mask + (size_t)(row0 + qi) * L + l0 + c4);
            u64 bits = ((u64)(mm.x != 0) << c4)       | ((u64)(mm.y != 0) << (c4 + 1))
                     | ((u64)(mm.z != 0) << (c4 + 2)) | ((u64)(mm.w != 0) << (c4 + 3));
            #pragma unroll
            for (int off = 1; off < 16; off <<= 1)
                bits |= __shfl_xor_sync(0xFFFFFFFFu, bits, off);
            if ((tid & 15) == 0) S->Mbits[qi] = bits;
        }
        __syncthreads();

        // ================= compute (two warp groups) =================
        if (tid < 256) {
            // ---- scores: 2q x 4k, strided k rows, f32x2 pairwise over d ----
            const float thr0 = S->thr[qa];
            const float thr1 = S->thr[qa + 1];
            const u64   Mb0  = S->Mbits[qa];
            const u64   Mb1  = S->Mbits[qa + 1];
            u64 sp0[4], sp1[4];
            #pragma unroll
            for (int j = 0; j < 4; j++) { sp0[j] = 0ull; sp1[j] = 0ull; }

            #pragma unroll 4
            for (int d = 0; d < D; d += 4) {
                ulonglong2 Q0 = *(const ulonglong2*)&S->Qs[qa][d];
                ulonglong2 Q1 = *(const ulonglong2*)&S->Qs[qa + 1][d];
                #pragma unroll
                for (int j = 0; j < 4; j++) {
                    ulonglong2 Kj = *(const ulonglong2*)&S->Ks[t15 + 16 * j][d];
                    fma2(sp0[j], Q0.x, Kj.x);
                    fma2(sp0[j], Q0.y, Kj.y);
                    fma2(sp1[j], Q1.x, Kj.x);
                    fma2(sp1[j], Q1.y, Kj.y);
                }
            }
            u64 w0 = 0ull, w1 = 0ull;
            #pragma unroll
            for (int j = 0; j < 4; j++) {
                int kp = t15 + 16 * j;
                float2 p0 = up2(sp0[j]);
                float  s0 = p0.x + p0.y;
                S->Ss[qa][kp] = s0;
                if (s0 > thr0 && ((Mb0 >> kp) & 1ull)) w0 |= 1ull << kp;
                float2 p1 = up2(sp1[j]);
                float  s1 = p1.x + p1.y;
                S->Ss[qa + 1][kp] = s1;
                if (s1 > thr1 && ((Mb1 >> kp) & 1ull)) w1 |= 1ull << kp;
            }
            if (w0) atomicOr(&S->cand[qa],     w0);
            if (w1) atomicOr(&S->cand[qa + 1], w1);
        } else {
            // ---- mask*V: 2q x 4d, predicated packed adds ----
            const u64 Mb0 = S->Mbits[qa];
            const u64 Mb1 = S->Mbits[qa + 1];
            const unsigned m0l = (unsigned)Mb0, m0h = (unsigned)(Mb0 >> 32);
            const unsigned m1l = (unsigned)Mb1, m1h = (unsigned)(Mb1 >> 32);
            #pragma unroll
            for (int l = 0; l < TK; l++) {
                ulonglong2 v2 = *(const ulonglong2*)&S->Vs[l][dc];
                unsigned t0 = ((l < 32) ? m0l : m0h) & (1u << (l & 31));
                unsigned t1 = ((l < 32) ? m1l : m1h) & (1u << (l & 31));
                madd2(mv[0], mv[1], t0, v2.x, v2.y);
                madd2(mv[2], mv[3], t1, v2.x, v2.y);
            }
        }
        __syncthreads();

        // ================= merge candidates =================
        if (tid < MQ) {
            const int qq = tid;
            u64 w = S->cand[qq];
            cntL += (float)__popcll(S->Mbits[qq]);
            while (w) {
                int kk = __ffsll((long long)w) - 1;
                w &= w - 1ull;
                float s = S->Ss[qq][kk];
                if (s > thrL) {
                    S->tsc[qq][minpos] = s;
                    S->tix[qq][minpos] = l0 + kk;
                    float nm = S->tsc[qq][0]; int np = 0;
                    #pragma unroll
                    for (int i = 1; i < TOPK; i++) {
                        float ti = S->tsc[qq][i];
                        if (ti < nm) { nm = ti; np = i; }
                    }
                    thrL = nm; minpos = np;
                }
            }
            S->thr[qq]  = thrL;
            S->cand[qq] = 0ull;
        }
        __syncthreads();
    }

    // ---- dump mask*V sums into Ss [q][d] ----
    if (tid >= 256) {
        float2 a = up2(mv[0]), bq = up2(mv[1]);
        *(float4*)&S->Ss[qa][dc] = make_float4(a.x, a.y, bq.x, bq.y);
        float2 c = up2(mv[2]), dq = up2(mv[3]);
        *(float4*)&S->Ss[qa + 1][dc] = make_float4(c.x, c.y, dq.x, dq.y);
    }
    if (tid < MQ) S->cnt[tid] = cntL;
    __syncthreads();

    // ---- epilogue: softmax over top-32, gather V, add mean ----
    const int wid  = tid >> 5;
    const int lane = tid & 31;
    const float* vb = v + kb;
    for (int qq = wid; qq < MQ; qq += (THREADS / 32)) {
        float s  = S->tsc[qq][lane];
        int   ix = S->tix[qq][lane];
        bool valid = (ix >= 0);
        float sv = valid ? s : NEG_INF;
        float m = sv;
        #pragma unroll
        for (int off = 16; off > 0; off >>= 1)
            m = fmaxf(m, __shfl_xor_sync(0xFFFFFFFFu, m, off));
        float e = valid ? expf(s - m) : 0.0f;
        float den = e;
        #pragma unroll
        for (int off = 16; off > 0; off >>= 1)
            den += __shfl_xor_sync(0xFFFFFFFFu, den, off);
        float w = (den > 0.0f) ? (e / den) : 0.0f;

        float a0 = 0.0f, a1 = 0.0f;
        #pragma unroll 1
        for (int i = 0; i < TOPK; i++) {
            float wi = __shfl_sync(0xFFFFFFFFu, w, i);
            int   ii = __shfl_sync(0xFFFFFFFFu, ix, i);
            if (ii >= 0) {
                const float* vr = vb + (size_t)ii * D;
                a0 = fmaf(wi, vr[lane],      a0);
                a1 = fmaf(wi, vr[lane + 32], a1);
            }
        }
        float c = fmaxf(S->cnt[qq], 1.0f);
        size_t obase = ((size_t)(row0 + qq)) * D;
        out[obase + lane]      = S->Ss[qq][lane]      / c + a0;
        out[obase + lane + 32] = S->Ss[qq][lane + 32] / c + a1;
    }
}

extern "C" void kernel_launch(void* const* d_in, const int* in_sizes, int n_in,
                              void* d_out, int out_size)
{
    const float* q = (const float*)d_in[0];
    const float* k = (const float*)d_in[1];
    const float* v = (const float*)d_in[2];
    const int*   mask = (const int*)d_in[3];
    float* out = (float*)d_out;

    int N    = in_sizes[0] / D;    // B * Lq
    int Ktot = in_sizes[1] / D;    // B * L
    int L    = in_sizes[3] / N;
    int B    = Ktot / L;
    int Lq   = N / B;

    int smem = (int)sizeof(Smem);
    cudaFuncSetAttribute(ga_kernel, cudaFuncAttributeMaxDynamicSharedMemorySize, smem);

    dim3 grid(Lq / MQ, B);
    ga_kernel<<<grid, THREADS, smem>>>(q, k, v, mask, out, B, Lq, L);
}

// round 7
// speedup vs baseline: 1.9598x; 1.3022x over previous
#include <cuda_runtime.h>
#include <math.h>

#define D        64
#define MQ       32
#define TK       64
#define TOPK     32
#define THREADS  512
#define NEG_INF  (-3.402823466e38f)

typedef unsigned long long u64;

struct __align__(16) Smem {
    float Qs[MQ][D + 4];          // pre-scaled q [q][d]
    float Ks[2][TK][D + 4];       // double-buffered k tile
    float Vs[2][TK][D];           // double-buffered v tile
    float Ss[2][MQ][D + 4];       // double-buffered scores [q][k]; Ss[0] reused for sums
    float tsc[MQ][TOPK];
    int   tix[MQ][TOPK];
    u64   Mbits[2][MQ];
    u64   cand[2][MQ];
    float thr[MQ];
    float cnt[MQ];
};

__device__ __forceinline__ void fma2(u64& d, u64 a, u64 b) {
    asm("fma.rn.f32x2 %0, %1, %2, %0;" : "+l"(d) : "l"(a), "l"(b));
}
__device__ __forceinline__ float2 up2(u64 a) {
    float2 r;
    asm("mov.b64 {%0,%1}, %2;" : "=f"(r.x), "=f"(r.y) : "l"(a));
    return r;
}
__device__ __forceinline__ void madd2(u64& a0, u64& a1, unsigned t, u64 vx, u64 vy) {
    asm volatile("{\n\t.reg .pred p;\n\tsetp.ne.u32 p, %2, 0;\n\t"
                 "@p add.rn.f32x2 %0, %0, %3;\n\t"
                 "@p add.rn.f32x2 %1, %1, %4;\n\t}"
                 : "+l"(a0), "+l"(a1) : "r"(t), "l"(vx), "l"(vy));
}
__device__ __forceinline__ void cp16(void* s, const void* g) {
    unsigned sa = (unsigned)__cvta_generic_to_shared(s);
    asm volatile("cp.async.cg.shared.global [%0], [%1], 16;" :: "r"(sa), "l"(g));
}

__global__ __launch_bounds__(THREADS)
void ga_kernel(const float* __restrict__ q, const float* __restrict__ k,
               const float* __restrict__ v, const int* __restrict__ mask,
               float* __restrict__ out, int B, int Lq, int L)
{
    extern __shared__ unsigned char smem_raw[];
    Smem* S = reinterpret_cast<Smem*>(smem_raw);

    const int tid  = threadIdx.x;
    const int b    = blockIdx.y;
    const int q0g  = blockIdx.x * MQ;
    const int row0 = b * Lq + q0g;
    const int NT   = L / TK;                    // number of tiles

    const int t15 = tid & 15;
    const int qa  = 2 * ((tid & 255) >> 4);     // score warps 0-7
    const int tv  = tid - 256;                  // V warps 8-11 (tv 0..127)
    const int qb  = 4 * (tv >> 4);
    const int dc  = 4 * (tv & 15);

    // ---- init ----
    for (int j = tid; j < MQ * D; j += THREADS) {
        int qi = j >> 6, d = j & 63;
        S->Qs[qi][d] = q[((size_t)row0 + qi) * D + d] * 0.125f;
    }
    for (int j = tid; j < MQ * TOPK; j += THREADS) {
        S->tsc[j >> 5][j & 31] = NEG_INF;
        S->tix[j >> 5][j & 31] = -1;
    }
    if (tid < MQ) {
        S->thr[tid]     = NEG_INF;
        S->cand[0][tid] = 0ull;
        S->cand[1][tid] = 0ull;
    }

    const size_t kb = (size_t)b * L * D;

    // ---- prologue: load tile 0 synchronously + Mbits[0] ----
    #pragma unroll
    for (int r = 0; r < 2; r++) {
        int idx4 = tid + THREADS * r;
        int i  = idx4 >> 4;
        int c4 = (idx4 & 15) << 2;
        *(float4*)&S->Ks[0][i][c4] = *(const float4*)(k + kb + (size_t)i * D + c4);
        *(float4*)&S->Vs[0][i][c4] = *(const float4*)(v + kb + (size_t)i * D + c4);
    }
    {
        int qi = tid >> 4, c4 = (tid & 15) << 2;
        int4 mm = *(const int4*)(mask + (size_t)(row0 + qi) * L + c4);
        u64 bits = ((u64)(mm.x != 0) << c4)       | ((u64)(mm.y != 0) << (c4 + 1))
                 | ((u64)(mm.z != 0) << (c4 + 2)) | ((u64)(mm.w != 0) << (c4 + 3));
        #pragma unroll
        for (int off = 1; off < 16; off <<= 1)
            bits |= __shfl_xor_sync(0xFFFFFFFFu, bits, off);
        if ((tid & 15) == 0) S->Mbits[0][qi] = bits;
    }
    __syncthreads();

    u64 mv[8];
    #pragma unroll
    for (int i = 0; i < 8; i++) mv[i] = 0ull;

    float thrL = NEG_INF;     // merge warp state (warp 12, lane = query)
    int   minpos = 0;
    float cntL = 0.0f;

    for (int t = 0; t < NT; t++) {
        const int p  = t & 1;
        const int pn = p ^ 1;
        const int l0 = t * TK;

        if (tid < 256) {
            // ======== score warps: 2q x 4k, strided k rows ========
            const float thr0 = S->thr[qa];
            const float thr1 = S->thr[qa + 1];
            const u64   Mb0  = S->Mbits[p][qa];
            const u64   Mb1  = S->Mbits[p][qa + 1];
            u64 sp0[4], sp1[4];
            #pragma unroll
            for (int j = 0; j < 4; j++) { sp0[j] = 0ull; sp1[j] = 0ull; }

            #pragma unroll 4
            for (int d = 0; d < D; d += 4) {
                ulonglong2 Q0 = *(const ulonglong2*)&S->Qs[qa][d];
                ulonglong2 Q1 = *(const ulonglong2*)&S->Qs[qa + 1][d];
                #pragma unroll
                for (int j = 0; j < 4; j++) {
                    ulonglong2 Kj = *(const ulonglong2*)&S->Ks[p][t15 + 16 * j][d];
                    fma2(sp0[j], Q0.x, Kj.x);
                    fma2(sp0[j], Q0.y, Kj.y);
                    fma2(sp1[j], Q1.x, Kj.x);
                    fma2(sp1[j], Q1.y, Kj.y);
                }
            }
            u64 w0 = 0ull, w1 = 0ull;
            #pragma unroll
            for (int j = 0; j < 4; j++) {
                int kp = t15 + 16 * j;
                float2 p0 = up2(sp0[j]);
                float  s0 = p0.x + p0.y;
                S->Ss[p][qa][kp] = s0;
                if (s0 > thr0 && ((Mb0 >> kp) & 1ull)) w0 |= 1ull << kp;
                float2 p1 = up2(sp1[j]);
                float  s1 = p1.x + p1.y;
                S->Ss[p][qa + 1][kp] = s1;
                if (s1 > thr1 && ((Mb1 >> kp) & 1ull)) w1 |= 1ull << kp;
            }
            if (w0) atomicOr(&S->cand[p][qa],     w0);
            if (w1) atomicOr(&S->cand[p][qa + 1], w1);
        } else if (tid < 384) {
            // ======== V warps: 4q x 4d, predicated packed adds ========
            unsigned mlo[4], mhi[4];
            #pragma unroll
            for (int qi = 0; qi < 4; qi++) {
                u64 M = S->Mbits[p][qb + qi];
                mlo[qi] = (unsigned)M;
                mhi[qi] = (unsigned)(M >> 32);
            }
            #pragma unroll
            for (int l = 0; l < TK; l++) {
                ulonglong2 v2 = *(const ulonglong2*)&S->Vs[p][l][dc];
                #pragma unroll
                for (int qi = 0; qi < 4; qi++) {
                    unsigned tb = ((l < 32) ? mlo[qi] : mhi[qi]) & (1u << (l & 31));
                    madd2(mv[2 * qi], mv[2 * qi + 1], tb, v2.x, v2.y);
                }
            }
        } else if (tid < 416) {
            // ======== merge warp: consume tile t-1, prefetch mask t+1 ========
            const int qq = tid - 384;
            if (t > 0) {
                u64 w = S->cand[pn][qq];
                S->cand[pn][qq] = 0ull;
                cntL += (float)__popcll(S->Mbits[pn][qq]);
                const int l0p = l0 - TK;
                while (w) {
                    int kk = __ffsll((long long)w) - 1;
                    w &= w - 1ull;
                    float s = S->Ss[pn][qq][kk];
                    if (s > thrL) {
                        S->tsc[qq][minpos] = s;
                        S->tix[qq][minpos] = l0p + kk;
                        float nm = S->tsc[qq][0]; int np = 0;
                        #pragma unroll
                        for (int i = 1; i < TOPK; i++) {
                            float ti = S->tsc[qq][i];
                            if (ti < nm) { nm = ti; np = i; }
                        }
                        thrL = nm; minpos = np;
                    }
                }
                S->thr[qq] = thrL;
            }
            if (t < NT - 1) {
                const int4* mp = (const int4*)(mask + (size_t)(row0 + qq) * L + l0 + TK);
                u64 bits = 0ull;
                #pragma unroll
                for (int c4 = 0; c4 < 16; c4++) {
                    int4 mm = mp[c4];
                    bits |= ((u64)(mm.x != 0) << (4 * c4))
                          | ((u64)(mm.y != 0) << (4 * c4 + 1))
                          | ((u64)(mm.z != 0) << (4 * c4 + 2))
                          | ((u64)(mm.w != 0) << (4 * c4 + 3));
                }
                S->Mbits[pn][qq] = bits;
            }
        } else {
            // ======== loader warps: cp.async next K/V tile ========
            if (t < NT - 1) {
                const int lt = tid - 416;                  // 0..95
                const size_t base = kb + (size_t)(l0 + TK) * D;
                for (int j = lt; j < 2048; j += 96) {
                    int jj = j & 1023;
                    int i  = jj >> 4;
                    int c4 = (jj & 15) << 2;
                    if (j < 1024) cp16(&S->Ks[pn][i][c4], k + base + (size_t)i * D + c4);
                    else          cp16(&S->Vs[pn][i][c4], v + base + (size_t)i * D + c4);
                }
                asm volatile("cp.async.commit_group;");
                asm volatile("cp.async.wait_group 0;");
            }
        }
        __syncthreads();
    }

    // ---- final merge (last tile) ----
    if (tid >= 384 && tid < 416) {
        const int qq = tid - 384;
        const int pl = (NT - 1) & 1;
        u64 w = S->cand[pl][qq];
        cntL += (float)__popcll(S->Mbits[pl][qq]);
        const int l0p = L - TK;
        while (w) {
            int kk = __ffsll((long long)w) - 1;
            w &= w - 1ull;
            float s = S->Ss[pl][qq][kk];
            if (s > thrL) {
                S->tsc[qq][minpos] = s;
                S->tix[qq][minpos] = l0p + kk;
                float nm = S->tsc[qq][0]; int np = 0;
                #pragma unroll
                for (int i = 1; i < TOPK; i++) {
                    float ti = S->tsc[qq][i];
                    if (ti < nm) { nm = ti; np = i; }
                }
                thrL = nm; minpos = np;
            }
        }
        S->cnt[qq] = cntL;
    }
    __syncthreads();   // Ss[] free after this point

    // ---- dump mask*V sums into Ss[0][q][d] ----
    if (tid >= 256 && tid < 384) {
        #pragma unroll
        for (int qi = 0; qi < 4; qi++) {
            float2 a = up2(mv[2 * qi]);
            float2 c = up2(mv[2 * qi + 1]);
            *(float4*)&S->Ss[0][qb + qi][dc] = make_float4(a.x, a.y, c.x, c.y);
        }
    }
    __syncthreads();

    // ---- epilogue: softmax over top-32, gather V, add mean ----
    const int wid  = tid >> 5;
    const int lane = tid & 31;
    const float* vb = v + kb;
    for (int qq = wid; qq < MQ; qq += (THREADS / 32)) {
        float s  = S->tsc[qq][lane];
        int   ix = S->tix[qq][lane];
        bool valid = (ix >= 0);
        float sv = valid ? s : NEG_INF;
        float m = sv;
        #pragma unroll
        for (int off = 16; off > 0; off >>= 1)
            m = fmaxf(m, __shfl_xor_sync(0xFFFFFFFFu, m, off));
        float e = valid ? expf(s - m) : 0.0f;
        float den = e;
        #pragma unroll
        for (int off = 16; off > 0; off >>= 1)
            den += __shfl_xor_sync(0xFFFFFFFFu, den, off);
        float w = (den > 0.0f) ? (e / den) : 0.0f;

        float a0 = 0.0f, a1 = 0.0f;
        #pragma unroll 1
        for (int i = 0; i < TOPK; i++) {
            float wi = __shfl_sync(0xFFFFFFFFu, w, i);
            int   ii = __shfl_sync(0xFFFFFFFFu, ix, i);
            if (ii >= 0) {
                const float* vr = vb + (size_t)ii * D;
                a0 = fmaf(wi, vr[lane],      a0);
                a1 = fmaf(wi, vr[lane + 32], a1);
            }
        }
        float c = fmaxf(S->cnt[qq], 1.0f);
        size_t obase = ((size_t)(row0 + qq)) * D;
        out[obase + lane]      = S->Ss[0][qq][lane]      / c + a0;
        out[obase + lane + 32] = S->Ss[0][qq][lane + 32] / c + a1;
    }
}

extern "C" void kernel_launch(void* const* d_in, const int* in_sizes, int n_in,
                              void* d_out, int out_size)
{
    const float* q = (const float*)d_in[0];
    const float* k = (const float*)d_in[1];
    const float* v = (const float*)d_in[2];
    const int*   mask = (const int*)d_in[3];
    float* out = (float*)d_out;

    int N    = in_sizes[0] / D;    // B * Lq
    int Ktot = in_sizes[1] / D;    // B * L
    int L    = in_sizes[3] / N;
    int B    = Ktot / L;
    int Lq   = N / B;

    int smem = (int)sizeof(Smem);
    cudaFuncSetAttribute(ga_kernel, cudaFuncAttributeMaxDynamicSharedMemorySize, smem);

    dim3 grid(Lq / MQ, B);
    ga_kernel<<<grid, THREADS, smem>>>(q, k, v, mask, out, B, Lq, L);
}